// round 2
// baseline (speedup 1.0000x reference)
#include <cuda_runtime.h>
#include <math.h>

// Problem constants
#define Bc 32
#define Nc 256
#define Tc 64
#define Mc 64
#define Hc 512
#define Wc 512
#define COL_THRESH 0.5f
#define CAND_PER_BLK 4   // candidates per block in kernel 1

// Scratch for raw per-(b,n) scores: [f_dis, f_pg, min_col_sq, f_dac]
__device__ float g_scratch[Bc * Nc * 4];

// ---------------------------------------------------------------------------
// Kernel 1: per-(b,n) raw score computation.
// grid = (N/CAND_PER_BLK, B), block = 64*CAND_PER_BLK threads.
// Each 64-thread group handles one candidate (one thread per timestep t).
// ---------------------------------------------------------------------------
__global__ __launch_bounds__(64 * CAND_PER_BLK) void score_kernel(
    const float* __restrict__ traj,     // (B,N,T,2)
    const float* __restrict__ goal,     // (B,2)
    const float* __restrict__ gt,       // (B,T,2)
    const float* __restrict__ obs,      // (B,M,2)
    const float* __restrict__ da)       // (B,H,W)
{
    const int b    = blockIdx.y;
    const int tid  = threadIdx.x;
    const int c    = tid >> 6;                      // candidate slot 0..3
    const int t    = tid & 63;                      // timestep 0..63
    const int n    = blockIdx.x * CAND_PER_BLK + c; // candidate index

    __shared__ float2 s_obs[Mc];
    __shared__ float2 s_gt[Tc];
    __shared__ float  s_red[CAND_PER_BLK][3][2];
    __shared__ float  s_pg[CAND_PER_BLK];

    // Stage obstacles + gt for this batch into shared (once per block)
    if (tid < Mc)      s_obs[tid] = ((const float2*)obs)[b * Mc + tid];
    else if (tid < Mc + Tc) s_gt[tid - Mc] = ((const float2*)gt)[b * Tc + (tid - Mc)];
    __syncthreads();

    // My trajectory point (coalesced float2 load)
    const float2 p = ((const float2*)traj)[((size_t)(b * Nc + n)) * Tc + t];

    // --- distance-to-GT term ---
    const float2 g = s_gt[t];
    float dxg = p.x - g.x, dyg = p.y - g.y;
    float dis = sqrtf(dxg * dxg + dyg * dyg);

    // --- progress term (endpoint only) ---
    if (t == Tc - 1) {
        const float2 gl = ((const float2*)goal)[b];
        float ex = p.x - gl.x, ey = p.y - gl.y;
        s_pg[c] = sqrtf(ex * ex + ey * ey);
    }

    // --- collision term: min squared distance over M obstacles ---
    float mind2 = 3.402823466e+38f;
#pragma unroll 8
    for (int m = 0; m < Mc; m++) {
        float2 o = s_obs[m];               // broadcast, conflict-free
        float ax = p.x - o.x;
        float ay = p.y - o.y;
        float d2 = fmaf(ay, ay, ax * ax);
        mind2 = fminf(mind2, d2);
    }

    // --- DAC term: gather from drivable mask ---
    // Match jnp op order exactly: ((x + 50.0)/100.0) * (w-1), int32 trunc, clip
    int xi = (int)((p.x + 50.0f) / 100.0f * (float)(Wc - 1));
    int yi = (int)((p.y + 50.0f) / 100.0f * (float)(Hc - 1));
    xi = min(max(xi, 0), Wc - 1);
    yi = min(max(yi, 0), Hc - 1);
    float dac = 1.0f - __ldg(&da[(size_t)b * (Hc * Wc) + yi * Wc + xi]);

    // --- reduction within the 64-thread candidate group ---
#pragma unroll
    for (int off = 16; off > 0; off >>= 1) {
        dis   += __shfl_xor_sync(0xFFFFFFFFu, dis, off);
        dac   += __shfl_xor_sync(0xFFFFFFFFu, dac, off);
        mind2  = fminf(mind2, __shfl_xor_sync(0xFFFFFFFFu, mind2, off));
    }
    const int lane = t & 31, w = t >> 5;   // warp-within-candidate: 0 or 1
    if (lane == 0) {
        s_red[c][0][w] = dis;
        s_red[c][1][w] = mind2;
        s_red[c][2][w] = dac;
    }
    __syncthreads();

    if (t == 0) {
        float f_dis   = (s_red[c][0][0] + s_red[c][0][1]) * (1.0f / Tc);
        float mcolsq  = fminf(s_red[c][1][0], s_red[c][1][1]);
        float f_dac   = (s_red[c][2][0] + s_red[c][2][1]) * (1.0f / Tc);
        int base = (b * Nc + n) * 4;
        g_scratch[base + 0] = f_dis;
        g_scratch[base + 1] = s_pg[c];
        g_scratch[base + 2] = mcolsq;
        g_scratch[base + 3] = f_dac;
    }
}

// ---------------------------------------------------------------------------
// Kernel 2: per-batch normalize, combine, argmax, gather best trajectory.
// grid = B, block = 256 threads (one per candidate n)
// ---------------------------------------------------------------------------
__device__ __forceinline__ void blk_minmax256(float v, float& mn, float& mx,
                                              float* s_mn, float* s_mx,
                                              int lane, int w)
{
    float a = v, b = v;
#pragma unroll
    for (int off = 16; off > 0; off >>= 1) {
        a = fminf(a, __shfl_xor_sync(0xFFFFFFFFu, a, off));
        b = fmaxf(b, __shfl_xor_sync(0xFFFFFFFFu, b, off));
    }
    if (lane == 0) { s_mn[w] = a; s_mx[w] = b; }
    __syncthreads();
    a = s_mn[lane & 7];
    b = s_mx[lane & 7];
#pragma unroll
    for (int off = 4; off > 0; off >>= 1) {
        a = fminf(a, __shfl_xor_sync(0xFFFFFFFFu, a, off));
        b = fmaxf(b, __shfl_xor_sync(0xFFFFFFFFu, b, off));
    }
    if (w == 0 && lane == 0) { s_mn[0] = a; s_mx[0] = b; }
    __syncthreads();
    mn = s_mn[0];
    mx = s_mx[0];
    __syncthreads();
}

__device__ __forceinline__ float norm01(float v, float mn, float mx)
{
    float d = mx - mn;
    d = (d == 0.0f) ? 1.0f : d;
    return (v - mn) / d;
}

__global__ __launch_bounds__(256) void select_kernel(
    const float* __restrict__ traj,  // (B,N,T,2)
    float* __restrict__ out)         // [B*T*2 best | B*N scores]
{
    const int b = blockIdx.x;
    const int n = threadIdx.x;  // 0..255
    const int lane = n & 31, w = n >> 5;

    __shared__ float s_mn[8], s_mx[8];
    __shared__ float s_bs[8];
    __shared__ int   s_bi[8];
    __shared__ int   s_best;

    const int base = (b * Nc + n) * 4;
    float f_dis = g_scratch[base + 0];
    float f_pg  = g_scratch[base + 1];
    float mcol  = sqrtf(g_scratch[base + 2]);
    float t     = mcol - COL_THRESH;
    float f_col = expf(-(t * t));
    float f_dac = g_scratch[base + 3];

    float mn, mx;
    float score = 0.0f;
    blk_minmax256(f_dis, mn, mx, s_mn, s_mx, lane, w);
    score += norm01(f_dis, mn, mx);
    blk_minmax256(f_pg, mn, mx, s_mn, s_mx, lane, w);
    score += norm01(f_pg, mn, mx);
    blk_minmax256(f_col, mn, mx, s_mn, s_mx, lane, w);
    score += norm01(f_col, mn, mx);
    blk_minmax256(f_dac, mn, mx, s_mn, s_mx, lane, w);
    score += norm01(f_dac, mn, mx);
    score = -score;

    // scores output region starts after best_trajectory block (B*T*2 floats)
    float* out_scores = out + (Bc * Tc * 2);
    out_scores[b * Nc + n] = score;

    // --- argmax with first-index tie-break (matches jnp.argmax) ---
    float bs = score;
    int   bi = n;
#pragma unroll
    for (int off = 16; off > 0; off >>= 1) {
        float os = __shfl_xor_sync(0xFFFFFFFFu, bs, off);
        int   oi = __shfl_xor_sync(0xFFFFFFFFu, bi, off);
        if (os > bs || (os == bs && oi < bi)) { bs = os; bi = oi; }
    }
    if (lane == 0) { s_bs[w] = bs; s_bi[w] = bi; }
    __syncthreads();
    if (w == 0) {
        bs = s_bs[lane & 7];
        bi = s_bi[lane & 7];
#pragma unroll
        for (int off = 4; off > 0; off >>= 1) {
            float os = __shfl_xor_sync(0xFFFFFFFFu, bs, off);
            int   oi = __shfl_xor_sync(0xFFFFFFFFu, bi, off);
            if (os > bs || (os == bs && oi < bi)) { bs = os; bi = oi; }
        }
        if (lane == 0) s_best = bi;
    }
    __syncthreads();

    // --- copy best trajectory: T*2 = 128 floats = 64 float2 ---
    const int best = s_best;
    if (n < Tc) {
        ((float2*)out)[b * Tc + n] =
            ((const float2*)traj)[((size_t)(b * Nc + best)) * Tc + n];
    }
}

// ---------------------------------------------------------------------------
// Launch
// ---------------------------------------------------------------------------
extern "C" void kernel_launch(void* const* d_in, const int* in_sizes, int n_in,
                              void* d_out, int out_size)
{
    const float* traj = (const float*)d_in[0];   // (B,N,T,2)
    const float* goal = (const float*)d_in[1];   // (B,2)
    const float* gt   = (const float*)d_in[2];   // (B,T,2)
    const float* obs  = (const float*)d_in[3];   // (B,M,2)
    const float* da   = (const float*)d_in[4];   // (B,H,W)
    float* out = (float*)d_out;

    dim3 g1(Nc / CAND_PER_BLK, Bc);
    score_kernel<<<g1, 64 * CAND_PER_BLK>>>(traj, goal, gt, obs, da);
    select_kernel<<<Bc, 256>>>(traj, out);
}